// round 1
// baseline (speedup 1.0000x reference)
#include <cuda_runtime.h>
#include <math.h>

#define BB  32
#define NSQ 1024
#define NCQ 1024
#define DD  256
#define DP1 257
#define KKW 128
#define KP1 129

// ----------------------------- scratch (static device globals; no runtime alloc) ---
static __device__ float2 g_c1 [(size_t)BB*NSQ*DD];
static __device__ float2 g_c1T[(size_t)BB*DD*NSQ];
static __device__ float  g_sT [(size_t)BB*DD*NSQ];
static __device__ float  g_real[(size_t)BB*NSQ*DD];
static __device__ float  g_Ls [(size_t)BB*NSQ*DP1];
static __device__ float  g_Lc [(size_t)BB*NCQ*DP1];
static __device__ float  g_Llin[(size_t)BB*NCQ*DP1];
static __device__ float  g_Yt [(size_t)BB*NSQ*KP1];
static __device__ float  g_Lb [(size_t)BB*NSQ*NCQ];
static __device__ float  g_xnr[BB*NSQ];
static __device__ float  g_xnc[BB*NCQ];
static __device__ float  g_Hsa[(size_t)BB*NSQ*KKW];
static __device__ float  g_Hca[(size_t)BB*NCQ*KKW];
static __device__ float  g_Mxs[(size_t)BB*NSQ*KKW];
static __device__ float  g_Mxc[(size_t)BB*NCQ*KKW];
static __device__ float  g_Hcm[(size_t)BB*KKW*NCQ];
static __device__ float  g_lgs[BB*NSQ];
static __device__ float  g_lgc[BB*NCQ];
static __device__ float  g_cs [BB*DP1];
static __device__ float  g_cc [BB*DP1];

// ----------------------------- helpers ---------------------------------------------
__device__ __forceinline__ float atanhc(float x){
    x = fminf(fmaxf(x, -1.f + 1e-5f), 1.f - 1e-5f);
    return 0.5f * (log1pf(x) - log1pf(-x));
}
__device__ __forceinline__ float gelu_exact(float v){
    return 0.5f * v * (1.f + erff(v * 0.70710678118654752f));
}
__device__ __forceinline__ float blockReduceSum(float v){
    __shared__ float sh[32];
    #pragma unroll
    for (int o = 16; o; o >>= 1) v += __shfl_down_sync(0xffffffffu, v, o);
    int lane = threadIdx.x & 31, w = threadIdx.x >> 5;
    if (lane == 0) sh[w] = v;
    __syncthreads();
    int nw = (blockDim.x + 31) >> 5;
    v = (threadIdx.x < (unsigned)nw) ? sh[threadIdx.x] : 0.f;
    if (w == 0){
        #pragma unroll
        for (int o = 16; o; o >>= 1) v += __shfl_down_sync(0xffffffffu, v, o);
        if (lane == 0) sh[0] = v;
    }
    __syncthreads();
    float r = sh[0];
    __syncthreads();
    return r;
}
__device__ __forceinline__ float blockReduceMax(float v){
    __shared__ float sh[32];
    #pragma unroll
    for (int o = 16; o; o >>= 1) v = fmaxf(v, __shfl_down_sync(0xffffffffu, v, o));
    int lane = threadIdx.x & 31, w = threadIdx.x >> 5;
    if (lane == 0) sh[w] = v;
    __syncthreads();
    int nw = (blockDim.x + 31) >> 5;
    v = (threadIdx.x < (unsigned)nw) ? sh[threadIdx.x] : -3.4e38f;
    if (w == 0){
        #pragma unroll
        for (int o = 16; o; o >>= 1) v = fmaxf(v, __shfl_down_sync(0xffffffffu, v, o));
        if (lane == 0) sh[0] = v;
    }
    __syncthreads();
    float r = sh[0];
    __syncthreads();
    return r;
}

// ----------------------------- FFT kernels -----------------------------------------
// FFT-256 along last axis, optional fused p_logmap0 (per row). out: (B,NS,D) complex.
__global__ void k_fft256(const float* __restrict__ in, float2* __restrict__ out, int do_log){
    __shared__ float2 sa[256];
    size_t row = blockIdx.x;
    const float* x = in + row * 256;
    int t = threadIdx.x;                       // 128 threads
    float v0 = x[t], v1 = x[t + 128];
    if (do_log){
        float ss = blockReduceSum(v0*v0 + v1*v1);
        float yn = sqrtf(fmaxf(ss, 1e-15f));
        float f  = atanhc(yn) / yn;
        v0 *= f; v1 *= f;
    }
    sa[__brev((unsigned)t) >> 24]        = make_float2(v0, 0.f);
    sa[__brev((unsigned)(t+128)) >> 24]  = make_float2(v1, 0.f);
    __syncthreads();
    for (int len = 2; len <= 256; len <<= 1){
        int half = len >> 1;
        int g = t / half, j = t - g*half;
        int pos = g*len + j;
        float sn, cs;
        sincosf(-6.283185307179586f * (float)j / (float)len, &sn, &cs);
        float2 u = sa[pos], w = sa[pos + half];
        float2 wv = make_float2(w.x*cs - w.y*sn, w.x*sn + w.y*cs);
        sa[pos]        = make_float2(u.x + wv.x, u.y + wv.y);
        sa[pos + half] = make_float2(u.x - wv.x, u.y - wv.y);
        __syncthreads();
    }
    out[row*256 + t]       = sa[t];
    out[row*256 + t + 128] = sa[t + 128];
}

// FFT-1024 on complex rows; emit real part only.
__global__ void k_fft1024(const float2* __restrict__ in, float* __restrict__ outr){
    __shared__ float2 sa[1024];
    size_t row = blockIdx.x;
    int t = threadIdx.x;                       // 512 threads
    float2 a0 = in[row*1024 + t];
    float2 a1 = in[row*1024 + t + 512];
    sa[__brev((unsigned)t) >> 22]        = a0;
    sa[__brev((unsigned)(t+512)) >> 22]  = a1;
    __syncthreads();
    for (int len = 2; len <= 1024; len <<= 1){
        int half = len >> 1;
        int g = t / half, j = t - g*half;
        int pos = g*len + j;
        float sn, cs;
        sincosf(-6.283185307179586f * (float)j / (float)len, &sn, &cs);
        float2 u = sa[pos], w = sa[pos + half];
        float2 wv = make_float2(w.x*cs - w.y*sn, w.x*sn + w.y*cs);
        sa[pos]        = make_float2(u.x + wv.x, u.y + wv.y);
        sa[pos + half] = make_float2(u.x - wv.x, u.y - wv.y);
        __syncthreads();
    }
    outr[row*1024 + t]       = sa[t].x;
    outr[row*1024 + t + 512] = sa[t + 512].x;
}

// tiled transposes: per batch (R,C) -> (C,R)
__global__ void k_transpose_c(const float2* __restrict__ in, float2* __restrict__ out, int R, int C){
    __shared__ float2 tile[32][33];
    int b = blockIdx.z;
    size_t base = (size_t)b * R * C;
    int c0 = blockIdx.x * 32, r0 = blockIdx.y * 32;
    for (int i = threadIdx.y; i < 32; i += 8)
        tile[i][threadIdx.x] = in[base + (size_t)(r0+i)*C + (c0+threadIdx.x)];
    __syncthreads();
    for (int i = threadIdx.y; i < 32; i += 8)
        out[base + (size_t)(c0+i)*R + (r0+threadIdx.x)] = tile[threadIdx.x][i];
}
__global__ void k_transpose_f(const float* __restrict__ in, float* __restrict__ out, int R, int C){
    __shared__ float tile[32][33];
    int b = blockIdx.z;
    size_t base = (size_t)b * R * C;
    int c0 = blockIdx.x * 32, r0 = blockIdx.y * 32;
    for (int i = threadIdx.y; i < 32; i += 8)
        tile[i][threadIdx.x] = in[base + (size_t)(r0+i)*C + (c0+threadIdx.x)];
    __syncthreads();
    for (int i = threadIdx.y; i < 32; i += 8)
        out[base + (size_t)(c0+i)*R + (r0+threadIdx.x)] = tile[threadIdx.x][i];
}

// euclid_to_lorentz: 256-wide row -> 257-wide Lorentz row
__global__ void k_e2l(const float* __restrict__ in, float* __restrict__ out){
    size_t row = blockIdx.x;
    int t = threadIdx.x;                       // 256
    float v = in[row*256 + t];
    float ss = blockReduceSum(v*v);
    float xn = sqrtf(fmaxf(ss, 1e-15f)) + 1e-5f;
    float scl = fminf(1.f, 2.0f / xn);
    v *= scl;
    float vn = sqrtf(fmaxf(ss*scl*scl, 1e-15f));
    float f = sinhf(vn) / vn;
    if (t == 0) out[row*DP1] = coshf(vn);
    out[row*DP1 + 1 + t] = f * v;
}

// ----------------------------- generic fp32 GEMM -----------------------------------
// C[M,N] = op(A) * op(B)^T-ish:
//  ATRANS=0: A is M x K (lda)    ATRANS=1: A is K x M (lda)
//  BTRANS=1: B is N x K (ldb)    BTRANS=0: B is K x N (ldb)
//  MODE: 0 plain, 1 +bias[n], 2 gelu except col 0 (col0 -> 0)
template<int ATRANS, int BTRANS, int MODE>
__global__ void k_gemm(const float* __restrict__ A, const float* __restrict__ Bm,
                       const float* __restrict__ bias, float* __restrict__ C,
                       int M, int N, int Klen, int lda, int ldb, int ldc,
                       long sA, long sB, long sC)
{
    __shared__ float Ash[8][132];
    __shared__ float Bsh[8][132];
    int bz = blockIdx.z;
    A  += (size_t)bz * sA;
    Bm += (size_t)bz * sB;
    C  += (size_t)bz * sC;
    int bm = blockIdx.y * 128, bn = blockIdx.x * 128;
    int tid = threadIdx.x, tx = tid & 15, ty = tid >> 4;
    float acc[8][8];
    #pragma unroll
    for (int i = 0; i < 8; i++)
        #pragma unroll
        for (int j = 0; j < 8; j++) acc[i][j] = 0.f;

    for (int k0 = 0; k0 < Klen; k0 += 8){
        #pragma unroll
        for (int i = 0; i < 4; i++){
            int e = tid + i*256;
            int mm, kk;
            if (ATRANS == 0){ kk = e & 7; mm = e >> 3; }
            else            { mm = e & 127; kk = e >> 7; }
            int gm = bm + mm, gk = k0 + kk;
            float av = 0.f;
            if (gm < M && gk < Klen)
                av = (ATRANS == 0) ? A[(size_t)gm*lda + gk] : A[(size_t)gk*lda + gm];
            Ash[kk][mm] = av;

            int nn, kb;
            if (BTRANS == 1){ kb = e & 7; nn = e >> 3; }
            else            { nn = e & 127; kb = e >> 7; }
            int gn = bn + nn, gk2 = k0 + kb;
            float bv = 0.f;
            if (gn < N && gk2 < Klen)
                bv = (BTRANS == 1) ? Bm[(size_t)gn*ldb + gk2] : Bm[(size_t)gk2*ldb + gn];
            Bsh[kb][nn] = bv;
        }
        __syncthreads();
        #pragma unroll
        for (int k = 0; k < 8; k++){
            float4 a0 = *(const float4*)&Ash[k][ty*8];
            float4 a1 = *(const float4*)&Ash[k][ty*8 + 4];
            float4 b0 = *(const float4*)&Bsh[k][tx*8];
            float4 b1 = *(const float4*)&Bsh[k][tx*8 + 4];
            float av[8] = {a0.x,a0.y,a0.z,a0.w,a1.x,a1.y,a1.z,a1.w};
            float bv[8] = {b0.x,b0.y,b0.z,b0.w,b1.x,b1.y,b1.z,b1.w};
            #pragma unroll
            for (int i = 0; i < 8; i++)
                #pragma unroll
                for (int j = 0; j < 8; j++)
                    acc[i][j] = fmaf(av[i], bv[j], acc[i][j]);
        }
        __syncthreads();
    }
    #pragma unroll
    for (int i = 0; i < 8; i++){
        int gm = bm + ty*8 + i;
        if (gm >= M) continue;
        #pragma unroll
        for (int j = 0; j < 8; j++){
            int gn = bn + tx*8 + j;
            if (gn >= N) continue;
            float v = acc[i][j];
            if (MODE == 1) v += bias[gn];
            if (MODE == 2) v = (gn == 0) ? 0.f : gelu_exact(v);
            C[(size_t)gm*ldc + gn] = v;
        }
    }
}

// ----------------------------- row-wise kernels ------------------------------------
__global__ void k_fix_time(float* __restrict__ Y){        // width 257, recompute time
    size_t row = blockIdx.x;
    int t = threadIdx.x;                                  // 256
    float sp = Y[row*DP1 + 1 + t];
    float S = blockReduceSum(sp*sp);
    if (t == 0) Y[row*DP1] = sqrtf(S + 1.f);
}
__global__ void k_poincare(const float* __restrict__ Y, float* __restrict__ out){ // 129 -> 128
    size_t row = blockIdx.x;
    int t = threadIdx.x;                                  // 128
    float sp = Y[row*KP1 + 1 + t];
    float S = blockReduceSum(sp*sp);
    float time = sqrtf(S + 1.f);
    out[row*KKW + t] = sp / (time + 1.f);
}
__global__ void k_rowfix(float* __restrict__ L, float* __restrict__ xnr){
    size_t row = blockIdx.x;
    int t = threadIdx.x;                                  // 256
    float* p = L + row*1024;
    float s = 0.f;
    #pragma unroll
    for (int i = 0; i < 4; i++){ float v = p[t + i*256]; s += v*v; }  // col0 currently 0
    float S = blockReduceSum(s);
    if (t == 0){
        p[0] = sqrtf(S + 1.f);
        xnr[row] = sqrtf(fmaxf(2.f*S + 1.f, 1e-15f));
    }
}
__global__ void k_colnorm(const float* __restrict__ L, float* __restrict__ xnc){
    int b = blockIdx.y;
    int m = blockIdx.x*256 + threadIdx.x;
    const float* base = L + (size_t)b*NSQ*NCQ + m;
    float cs = 0.f;
    for (int n = 0; n < NSQ; n++){ float v = base[(size_t)n*NCQ]; cs += v*v; }
    xnc[b*NCQ + m] = sqrtf(fmaxf(cs, 1e-15f));
}
// mobius_matvec finalize (in-place): row width 128
__global__ void k_mfin(float* __restrict__ Mx, const float* __restrict__ xna){
    size_t row = blockIdx.x;
    int t = threadIdx.x;                                  // 128
    float v = Mx[row*KKW + t];
    float mm = blockReduceSum(v*v);
    float mxn = sqrtf(fmaxf(mm, 1e-15f));
    float xn = xna[row];
    float s = tanhf(mxn / xn * atanhc(xn)) / mxn;
    Mx[row*KKW + t] = v * s;
}
// mobius_add + p_logmap0 + gelu + p_expmap0 + As logit (128-wide rows)
__global__ void k_hs(const float* __restrict__ Hsa, const float* __restrict__ Yb,
                     const float* __restrict__ whs, float* __restrict__ lg){
    size_t row = blockIdx.x;
    int t = threadIdx.x;                                  // 128
    float x = Hsa[row*KKW + t];
    float y = Yb [row*KKW + t];
    float xy = blockReduceSum(x*y);
    float x2 = blockReduceSum(x*x);
    float y2 = blockReduceSum(y*y);
    float den = fmaxf(1.f + 2.f*xy + x2*y2, 1e-15f);
    float h = ((1.f + 2.f*xy + y2)*x + (1.f - x2)*y) / den;
    float hn = sqrtf(fmaxf(blockReduceSum(h*h), 1e-15f));
    float u = atanhc(hn) / hn * h;
    float g = gelu_exact(u);
    float gn = sqrtf(fmaxf(blockReduceSum(g*g), 1e-15f));
    float hs = tanhf(gn) / gn * g;
    float mx = blockReduceSum(hs * whs[t]);
    float xn = sqrtf(fmaxf(blockReduceSum(hs*hs), 1e-15f));
    if (t == 0){
        float mxn = sqrtf(fmaxf(mx*mx, 1e-15f));
        lg[row] = tanhf(mxn / xn * atanhc(xn)) * mx / mxn;
    }
}
// Hc path: rows over NC=1024 in transposed space; write Hc (B,K,NC)
__global__ void k_hc(const float* __restrict__ Hca, const float* __restrict__ Yb,
                     float* __restrict__ Hc){
    int bj = blockIdx.x;
    int b = bj >> 7, j = bj & 127;
    int t = threadIdx.x;                                  // 256
    float x[4], y[4];
    #pragma unroll
    for (int i = 0; i < 4; i++){
        int m = t + i*256;
        size_t idx = ((size_t)(b*NCQ + m))*KKW + j;
        x[i] = Hca[idx]; y[i] = Yb[idx];
    }
    float sxy = 0.f, sx2 = 0.f, sy2 = 0.f;
    #pragma unroll
    for (int i = 0; i < 4; i++){ sxy += x[i]*y[i]; sx2 += x[i]*x[i]; sy2 += y[i]*y[i]; }
    float xy = blockReduceSum(sxy);
    float x2 = blockReduceSum(sx2);
    float y2 = blockReduceSum(sy2);
    float den = fmaxf(1.f + 2.f*xy + x2*y2, 1e-15f);
    float c1 = 1.f + 2.f*xy + y2, c2 = 1.f - x2;
    float h[4], hh = 0.f;
    #pragma unroll
    for (int i = 0; i < 4; i++){ h[i] = (c1*x[i] + c2*y[i]) / den; hh += h[i]*h[i]; }
    float hn = sqrtf(fmaxf(blockReduceSum(hh), 1e-15f));
    float fa = atanhc(hn) / hn;
    float g[4], gg = 0.f;
    #pragma unroll
    for (int i = 0; i < 4; i++){ g[i] = gelu_exact(fa*h[i]); gg += g[i]*g[i]; }
    float gn = sqrtf(fmaxf(blockReduceSum(gg), 1e-15f));
    float fb = tanhf(gn) / gn;
    #pragma unroll
    for (int i = 0; i < 4; i++)
        Hc[((size_t)(b*KKW + j))*NCQ + (t + i*256)] = fb * g[i];
}
// Ac logits: per (b,m) reduce over j of Hc[b,j,m]
__global__ void k_ac(const float* __restrict__ Hc, const float* __restrict__ whc,
                     float* __restrict__ lg){
    __shared__ float wsh[KKW];
    int b = blockIdx.y;
    int m = blockIdx.x*256 + threadIdx.x;
    if (threadIdx.x < KKW) wsh[threadIdx.x] = whc[threadIdx.x];
    __syncthreads();
    const float* base = Hc + (size_t)b*KKW*NCQ + m;
    float mx = 0.f, ss = 0.f;
    #pragma unroll 4
    for (int j = 0; j < KKW; j++){
        float v = base[(size_t)j*NCQ];
        mx += v * wsh[j]; ss += v*v;
    }
    float xn = sqrtf(fmaxf(ss, 1e-15f));
    float mxn = sqrtf(fmaxf(mx*mx, 1e-15f));
    lg[b*NCQ + m] = tanhf(mxn / xn * atanhc(xn)) * mx / mxn;
}
__global__ void k_softmax(const float* __restrict__ lg, float* __restrict__ out){
    int b = blockIdx.x, t = threadIdx.x;                  // 256
    float l[4];
    float lm = -3.4e38f;
    #pragma unroll
    for (int i = 0; i < 4; i++){ l[i] = lg[b*1024 + t + i*256]; lm = fmaxf(lm, l[i]); }
    float M = blockReduceMax(lm);
    float es = 0.f, e[4];
    #pragma unroll
    for (int i = 0; i < 4; i++){ e[i] = expf(l[i] - M); es += e[i]; }
    float S = blockReduceSum(es);
    #pragma unroll
    for (int i = 0; i < 4; i++) out[b*1024 + t + i*256] = e[i] / S;
}
__global__ void k_centroid(const float* __restrict__ Lx, const float* __restrict__ w,
                           float* __restrict__ co){
    __shared__ float wsh[NSQ];
    __shared__ float t0sh;
    int b = blockIdx.x, t = threadIdx.x;                  // 288 threads, t<257 active
    for (int i = t; i < NSQ; i += blockDim.x) wsh[i] = w[(size_t)b*NSQ + i];
    __syncthreads();
    float acc = 0.f;
    if (t < DP1){
        const float* base = Lx + (size_t)b*NSQ*DP1 + t;
        for (int n = 0; n < NSQ; n++) acc += wsh[n] * base[(size_t)n*DP1];
    }
    float sp = (t >= 1 && t < DP1) ? acc*acc : 0.f;
    float ssp = blockReduceSum(sp);
    if (t == 0) t0sh = acc;
    __syncthreads();
    float inner = -t0sh*t0sh + ssp;
    float den = sqrtf(fmaxf(fabsf(inner), 1e-8f));
    if (t < DP1) co[(size_t)b*DP1 + t] = acc / den;
}
__global__ void k_concat(const float* __restrict__ cs, const float* __restrict__ cc,
                         float* __restrict__ out){
    int b = blockIdx.x, t = threadIdx.x;                  // 256
    float t0s = cs[(size_t)b*DP1];
    float t0c = cc[(size_t)b*DP1];
    float sps = cs[(size_t)b*DP1 + 1 + t];
    float spc = cc[(size_t)b*DP1 + 1 + t];
    float ns  = sqrtf(fmaxf(blockReduceSum(sps*sps), 1e-15f));
    float ncv = sqrtf(fmaxf(blockReduceSum(spc*spc), 1e-15f));
    float zs = acoshf(fmaxf(t0s, 1.f + 1e-7f)) * sps / ns;
    float zc = acoshf(fmaxf(t0c, 1.f + 1e-7f)) * spc / ncv;
    float vn = sqrtf(fmaxf(blockReduceSum(zs*zs + zc*zc), 1e-15f));
    float f = sinhf(vn) / vn;
    float* o = out + (size_t)b*513;
    if (t == 0) o[0] = coshf(vn);
    o[1 + t]       = f * zs;
    o[1 + DD + t]  = f * zc;
}

// ----------------------------- launch ----------------------------------------------
extern "C" void kernel_launch(void* const* d_in, const int* in_sizes, int n_in,
                              void* d_out, int out_size)
{
    const float* sent = (const float*)d_in[0];
    const float* comm = (const float*)d_in[1];
    const float* WlW  = (const float*)d_in[2];
    const float* Wlb  = (const float*)d_in[3];
    const float* WcW  = (const float*)d_in[4];
    const float* Wcb  = (const float*)d_in[5];
    const float* WsW  = (const float*)d_in[6];
    const float* Wsb  = (const float*)d_in[7];
    const float* whs  = (const float*)d_in[8];
    const float* whc  = (const float*)d_in[9];
    float* out = (float*)d_out;
    (void)in_sizes; (void)n_in; (void)out_size;

    float2 *c1, *c1T;
    float *sT, *rl, *Ls, *Lc, *Llin, *Yt, *Lb, *xnr, *xnc, *Hsa, *Hca, *Mxs, *Mxc, *Hcm,
          *lgs, *lgc, *cs, *cc;
    cudaGetSymbolAddress((void**)&c1,  g_c1);
    cudaGetSymbolAddress((void**)&c1T, g_c1T);
    cudaGetSymbolAddress((void**)&sT,  g_sT);
    cudaGetSymbolAddress((void**)&rl,  g_real);
    cudaGetSymbolAddress((void**)&Ls,  g_Ls);
    cudaGetSymbolAddress((void**)&Lc,  g_Lc);
    cudaGetSymbolAddress((void**)&Llin,g_Llin);
    cudaGetSymbolAddress((void**)&Yt,  g_Yt);
    cudaGetSymbolAddress((void**)&Lb,  g_Lb);
    cudaGetSymbolAddress((void**)&xnr, g_xnr);
    cudaGetSymbolAddress((void**)&xnc, g_xnc);
    cudaGetSymbolAddress((void**)&Hsa, g_Hsa);
    cudaGetSymbolAddress((void**)&Hca, g_Hca);
    cudaGetSymbolAddress((void**)&Mxs, g_Mxs);
    cudaGetSymbolAddress((void**)&Mxc, g_Mxc);
    cudaGetSymbolAddress((void**)&Hcm, g_Hcm);
    cudaGetSymbolAddress((void**)&lgs, g_lgs);
    cudaGetSymbolAddress((void**)&lgc, g_lgc);
    cudaGetSymbolAddress((void**)&cs,  g_cs);
    cudaGetSymbolAddress((void**)&cc,  g_cc);

    const int AS_OFF = BB*513;             // 16416
    const int AC_OFF = AS_OFF + BB*NSQ;    // 49184

    // ---- FFT2 + euclid_to_lorentz, both branches (buffers reused sequentially) ----
    for (int branch = 0; branch < 2; branch++){
        const float* inp = branch ? comm : sent;
        float* Lout = branch ? Lc : Ls;
        int dolog = branch ? 1 : 0;
        k_fft256<<<BB*NSQ, 128>>>(inp, c1, dolog);
        k_transpose_c<<<dim3(DD/32, NSQ/32, BB), dim3(32,8)>>>(c1, c1T, NSQ, DD);
        k_fft1024<<<BB*DD, 512>>>(c1T, sT);
        k_transpose_f<<<dim3(NSQ/32, DD/32, BB), dim3(32,8)>>>(sT, rl, DD, NSQ);
        k_e2l<<<BB*NSQ, 256>>>(rl, Lout);
    }

    // ---- linear layers ----
    k_gemm<0,1,1><<<dim3(3,256,1),256>>>(Lc, WlW, Wlb, Llin,
        BB*NCQ, DP1, DP1, DP1, DP1, DP1, 0, 0, 0);
    k_fix_time<<<BB*NCQ, 256>>>(Llin);

    k_gemm<0,1,1><<<dim3(2,256,1),256>>>(Ls, WsW, Wsb, Yt,
        BB*NSQ, KP1, DP1, DP1, DP1, KP1, 0, 0, 0);
    k_poincare<<<BB*NSQ, 128>>>(Yt, Hsa);

    k_gemm<0,1,1><<<dim3(2,256,1),256>>>(Lc, WcW, Wcb, Yt,
        BB*NCQ, KP1, DP1, DP1, DP1, KP1, 0, 0, 0);
    k_poincare<<<BB*NCQ, 128>>>(Yt, Hca);

    // ---- big einsum + lorentz_act (fused gelu epilogue) ----
    k_gemm<0,1,2><<<dim3(8,8,BB),256>>>(Ls, Llin, nullptr, Lb,
        NSQ, NCQ, DP1, DP1, DP1, NCQ,
        (long)NSQ*DP1, (long)NCQ*DP1, (long)NSQ*NCQ);
    k_rowfix<<<BB*NSQ, 256>>>(Lb, xnr);
    k_colnorm<<<dim3(NCQ/256, BB), 256>>>(Lb, xnc);

    // ---- mobius_matvec GEMMs ----
    k_gemm<0,0,0><<<dim3(1,8,BB),256>>>(Lb, Hca, nullptr, Mxs,
        NSQ, KKW, NCQ, NCQ, KKW, KKW,
        (long)NSQ*NCQ, (long)NCQ*KKW, (long)NSQ*KKW);
    k_gemm<1,0,0><<<dim3(1,8,BB),256>>>(Lb, Hsa, nullptr, Mxc,
        NCQ, KKW, NSQ, NCQ, KKW, KKW,
        (long)NSQ*NCQ, (long)NSQ*KKW, (long)NCQ*KKW);
    k_mfin<<<BB*NSQ, 128>>>(Mxs, xnr);
    k_mfin<<<BB*NCQ, 128>>>(Mxc, xnc);

    // ---- mobius_add + gelu pipeline + attention logits ----
    k_hs<<<BB*NSQ, 128>>>(Hsa, Mxs, whs, lgs);
    k_hc<<<BB*KKW, 256>>>(Hca, Mxc, Hcm);
    k_ac<<<dim3(NCQ/256, BB), 256>>>(Hcm, whc, lgc);

    // ---- softmaxes straight into output ----
    k_softmax<<<BB, 256>>>(lgs, out + AS_OFF);
    k_softmax<<<BB, 256>>>(lgc, out + AC_OFF);

    // ---- centroids + concat ----
    k_centroid<<<BB, 288>>>(Ls, out + AS_OFF, cs);
    k_centroid<<<BB, 288>>>(Lc, out + AC_OFF, cc);
    k_concat<<<BB, 256>>>(cs, cc, out);
}